// round 8
// baseline (speedup 1.0000x reference)
#include <cuda_runtime.h>
#include <cuda_fp16.h>
#include <math.h>

#define NN   100000
#define NE   1600000
#define INF  64
#define HIDD 128
#define NCLS 10
#define NCP  12
#define NB   ((NN + 255) / 256)     // 391 scan blocks
#define FULL 0xffffffffu

// packed f32x2 helpers (FFMA2 — ptxas never emits this from C++)
__device__ __forceinline__ unsigned long long f2pk(float lo, float hi) {
    unsigned long long r;
    asm("mov.b64 %0, {%1, %2};" : "=l"(r) : "f"(lo), "f"(hi));
    return r;
}
__device__ __forceinline__ void ffma2(unsigned long long& d,
                                      unsigned long long a,
                                      unsigned long long b) {
    asm("fma.rn.f32x2 %0, %1, %2, %0;" : "+l"(d) : "l"(a), "l"(b));
}
__device__ __forceinline__ float2 f2unpk(unsigned long long v) {
    float lo, hi;
    asm("mov.b64 {%0, %1}, %2;" : "=f"(lo), "=f"(hi) : "l"(v));
    return make_float2(lo, hi);
}

// ---------------- scratch (no allocations allowed) ----------------
__device__ int   g_is64;
__device__ int   g_cnt[NN];
__device__ int   g_cur[NN];
__device__ int   g_offs[NN + 1];
__device__ int   g_bsum[NB];
__device__ int   g_bpre[NB];
__device__ float g_dinv[NN];
__device__ int   g_rows[NE];
__device__ int   g_cols[NE];
__device__ int   g_msrc[NE];          // 6.4 MB : CSR src per slot
__device__ __half2 g_xh[NN * 32];     // 12.8 MB : xs = dinv*x in half
__device__ float4 g_agg1[NN * (INF / 4)];          // 25.6 MB
__device__ float4 g_h1[(size_t)NN * (HIDD / 4)];   // 51.2 MB
__device__ float g_t2s[NN * NCP];                  // 4.8 MB : dinv * (h1 @ W2), stride 12
__device__ float g_out2p[NN * NCP];                // 4.8 MB
__device__ float g_acc[NCLS];

// ---------------- kernels ----------------

__global__ void k_init(const void* __restrict__ ei_raw) {
    __shared__ int s_nz;
    int tid = threadIdx.x;
    int i = blockIdx.x * blockDim.x + tid;
    if (i < NN) { g_cnt[i] = 0; g_cur[i] = 0; }
    if (i < NCLS) g_acc[i] = 0.0f;
    if (tid == 0) s_nz = 0;
    __syncthreads();
    if (blockIdx.x == 0) {
        const unsigned int* w = (const unsigned int*)ei_raw;
        if (w[tid * 2 + 1] != 0u) atomicAdd(&s_nz, 1);
    }
    __syncthreads();
    if (blockIdx.x == 0 && tid == 0) g_is64 = (s_nz == 0) ? 1 : 0;
}

__global__ void k_edges_degree(const void* __restrict__ ei_raw) {
    int e = blockIdx.x * blockDim.x + threadIdx.x;
    if (e >= NE) return;
    int r, c;
    if (g_is64) {
        const long long* ei = (const long long*)ei_raw;
        r = (int)ei[e];  c = (int)ei[NE + e];
    } else {
        const int* ei = (const int*)ei_raw;
        r = ei[e];       c = ei[NE + e];
    }
    r = min(max(r, 0), NN - 1);
    c = min(max(c, 0), NN - 1);
    g_rows[e] = r;
    g_cols[e] = c;
    atomicAdd(&g_cnt[c], 1);
}

__global__ void k_scanA() {
    __shared__ int s[256];
    int tid = threadIdx.x;
    int i = blockIdx.x * 256 + tid;
    int v = (i < NN) ? g_cnt[i] : 0;
    if (i < NN) g_dinv[i] = rsqrtf((float)(v + 1));
    s[tid] = v;
    __syncthreads();
    #pragma unroll
    for (int st = 1; st < 256; st <<= 1) {
        int t = (tid >= st) ? s[tid - st] : 0;
        __syncthreads();
        s[tid] += t;
        __syncthreads();
    }
    if (i < NN) g_offs[i] = s[tid] - v;
    if (tid == 255) g_bsum[blockIdx.x] = s[255];
}

__global__ void k_scanB() {
    __shared__ int s[512];
    int tid = threadIdx.x;
    int v = (tid < NB) ? g_bsum[tid] : 0;
    s[tid] = v;
    __syncthreads();
    #pragma unroll
    for (int st = 1; st < 512; st <<= 1) {
        int t = (tid >= st) ? s[tid - st] : 0;
        __syncthreads();
        s[tid] += t;
        __syncthreads();
    }
    if (tid < NB) g_bpre[tid] = s[tid] - v;
    if (tid == 0) g_offs[NN] = NE;
}

__global__ void k_scanC() {
    int i = blockIdx.x * blockDim.x + threadIdx.x;
    if (i < NN) g_offs[i] += g_bpre[i >> 8];
}

__global__ void k_xhalf(const float* __restrict__ x) {
    int i = blockIdx.x * blockDim.x + threadIdx.x;   // NN*32
    if (i < NN * 32) {
        int node = i >> 5;
        float d = g_dinv[node];
        float2 v = ((const float2*)x)[i];
        g_xh[i] = __floats2half2_rn(d * v.x, d * v.y);
    }
}

__global__ void k_fill() {
    int e = blockIdx.x * blockDim.x + threadIdx.x;
    if (e >= NE) return;
    int c = g_cols[e];
    int pos = g_offs[c] + atomicAdd(&g_cur[c], 1);
    g_msrc[pos] = g_rows[e];
}

// layer-1 aggregation: warp per dest; 4x unrolled, batched loads (MLP=4)
__global__ void k_gather1() {
    int wid  = (blockIdx.x * blockDim.x + threadIdx.x) >> 5;
    int lane = threadIdx.x & 31;
    if (wid >= NN) return;
    int d = wid;
    float2 acc = __half22float2(g_xh[d * 32 + lane]);   // self term xs[d]
    float2 acc2 = make_float2(0.f, 0.f);
    int beg = g_offs[d];
    int deg = g_offs[d + 1] - beg;
    for (int base = 0; base < deg; base += 32) {
        int rem = deg - base;
        int cnt = rem < 32 ? rem : 32;
        int m = (lane < cnt) ? g_msrc[beg + base + lane] : 0;
        int j = 0;
        for (; j + 4 <= cnt; j += 4) {
            int s0 = __shfl_sync(FULL, m, j);
            int s1 = __shfl_sync(FULL, m, j + 1);
            int s2 = __shfl_sync(FULL, m, j + 2);
            int s3 = __shfl_sync(FULL, m, j + 3);
            __half2 v0 = g_xh[s0 * 32 + lane];
            __half2 v1 = g_xh[s1 * 32 + lane];
            __half2 v2 = g_xh[s2 * 32 + lane];
            __half2 v3 = g_xh[s3 * 32 + lane];
            float2 f0 = __half22float2(v0);
            float2 f1 = __half22float2(v1);
            float2 f2 = __half22float2(v2);
            float2 f3 = __half22float2(v3);
            acc.x  += f0.x + f1.x;  acc.y  += f0.y + f1.y;
            acc2.x += f2.x + f3.x;  acc2.y += f2.y + f3.y;
        }
        for (; j < cnt; j++) {
            int src = __shfl_sync(FULL, m, j);
            float2 v = __half22float2(g_xh[src * 32 + lane]);
            acc.x += v.x;  acc.y += v.y;
        }
    }
    float dd = g_dinv[d];
    acc.x = (acc.x + acc2.x) * dd;
    acc.y = (acc.y + acc2.y) * dd;
    ((float2*)g_agg1)[d * 32 + lane] = acc;
}

// h1 = relu(agg1 @ W1 + b1), 64x128 tile, 256 threads, FFMA2 inner
__global__ void k_gemm1(const float* __restrict__ W1, const float* __restrict__ b1) {
    __shared__ float As[64 * 64];
    __shared__ float Bs[64 * 128];
    int tid = threadIdx.x;
    int bnode = blockIdx.x * 64;

    for (int t = tid; t < (64 * 128) / 4; t += 256)
        ((float4*)Bs)[t] = ((const float4*)W1)[t];
    for (int t = tid; t < 64 * 16; t += 256) {
        int lr = t >> 4, q = t & 15;
        int node = bnode + lr;
        float4 v = (node < NN) ? g_agg1[node * 16 + q]
                               : make_float4(0.f, 0.f, 0.f, 0.f);
        ((float4*)As)[t] = v;
    }
    __syncthreads();

    int tx = tid & 31, ty = tid >> 5;
    unsigned long long a01[8], a23[8];
    #pragma unroll
    for (int i = 0; i < 8; i++) { a01[i] = 0ull; a23[i] = 0ull; }

    #pragma unroll 4
    for (int k = 0; k < 64; k++) {
        float4 bb = ((const float4*)Bs)[k * 32 + tx];
        unsigned long long b01 = f2pk(bb.x, bb.y);
        unsigned long long b23 = f2pk(bb.z, bb.w);
        #pragma unroll
        for (int i = 0; i < 8; i++) {
            float a = As[(ty * 8 + i) * 64 + k];
            unsigned long long aa = f2pk(a, a);
            ffma2(a01[i], aa, b01);
            ffma2(a23[i], aa, b23);
        }
    }

    float4 bias = ((const float4*)b1)[tx];
    #pragma unroll
    for (int i = 0; i < 8; i++) {
        int node = bnode + ty * 8 + i;
        if (node < NN) {
            float2 p = f2unpk(a01[i]);
            float2 q = f2unpk(a23[i]);
            float4 o;
            o.x = fmaxf(p.x + bias.x, 0.0f);
            o.y = fmaxf(p.y + bias.y, 0.0f);
            o.z = fmaxf(q.x + bias.z, 0.0f);
            o.w = fmaxf(q.y + bias.w, 0.0f);
            g_h1[(size_t)node * 32 + tx] = o;
        }
    }
}

// t2s = dinv * (h1 @ W2), stride-12 rows
__global__ void k_gemm2(const float* __restrict__ W2) {
    __shared__ float Ws[HIDD * NCLS];
    int tid = threadIdx.x;
    for (int t = tid; t < HIDD * NCLS; t += blockDim.x) Ws[t] = W2[t];
    __syncthreads();
    int node = blockIdx.x * blockDim.x + tid;
    if (node >= NN) return;
    float acc[NCLS];
    #pragma unroll
    for (int c = 0; c < NCLS; c++) acc[c] = 0.0f;
    const float4* row = &g_h1[(size_t)node * 32];
    #pragma unroll 8
    for (int kk = 0; kk < 32; kk++) {
        float4 h = row[kk];
        const float* w = &Ws[kk * 4 * NCLS];
        #pragma unroll
        for (int c = 0; c < NCLS; c++)
            acc[c] += h.x * w[c] + h.y * w[NCLS + c] + h.z * w[2 * NCLS + c] + h.w * w[3 * NCLS + c];
    }
    float d = g_dinv[node];
    #pragma unroll
    for (int c = 0; c < NCLS; c++) g_t2s[node * NCP + c] = d * acc[c];
}

// layer-2: out2[d] = dinv[d]*(t2s[d] + sum_edges t2s[src]) + b2; 2x unrolled
__global__ void k_gather2(const float* __restrict__ b2) {
    int wid  = (blockIdx.x * blockDim.x + threadIdx.x) >> 5;
    int lane = threadIdx.x & 31;
    if (wid >= NN) return;
    int d = wid;
    int s = lane / 10;          // 0..2 active, 3 for lanes 30,31
    int c = lane - s * 10;
    float acc = 0.0f, accB = 0.0f;
    int beg = g_offs[d];
    int deg = g_offs[d + 1] - beg;
    for (int base = 0; base < deg; base += 32) {
        int rem = deg - base;
        int cnt = rem < 32 ? rem : 32;
        int m = (lane < cnt) ? g_msrc[beg + base + lane] : 0;
        int iters = (cnt + 2) / 3;
        int jj = 0;
        for (; jj + 2 <= iters; jj += 2) {
            int j0 = jj * 3 + s;
            int j1 = j0 + 3;
            int s0 = __shfl_sync(FULL, m, j0 < 31 ? j0 : 31);
            int s1 = __shfl_sync(FULL, m, j1 < 31 ? j1 : 31);
            float t0 = 0.f, t1 = 0.f;
            if (s < 3 && j0 < cnt) t0 = g_t2s[s0 * NCP + c];
            if (s < 3 && j1 < cnt) t1 = g_t2s[s1 * NCP + c];
            acc += t0;
            accB += t1;
        }
        for (; jj < iters; jj++) {
            int j = jj * 3 + s;
            int src = __shfl_sync(FULL, m, j < 31 ? j : 31);
            if (s < 3 && j < cnt) acc += g_t2s[src * NCP + c];
        }
    }
    acc += accB;
    float a1 = __shfl_sync(FULL, acc, (lane + 10) & 31);
    float a2 = __shfl_sync(FULL, acc, (lane + 20) & 31);
    if (lane < 10) {
        float dd = g_dinv[d];
        g_out2p[d * NCP + lane] =
            dd * (acc + a1 + a2 + g_t2s[d * NCP + lane]) + b2[lane];
    }
}

// per-node log_softmax, block-reduce per class, atomic into g_acc
__global__ void k_final() {
    __shared__ float sred[NCLS * 256];
    int tid = threadIdx.x;
    int node = blockIdx.x * 256 + tid;
    float loc[NCLS];
    #pragma unroll
    for (int c = 0; c < NCLS; c++) loc[c] = 0.0f;
    if (node < NN) {
        const float* rowp = &g_out2p[node * NCP];
        float v[NCLS];
        float m = -1e30f;
        #pragma unroll
        for (int c = 0; c < NCLS; c++) {
            v[c] = rowp[c];
            m = fmaxf(m, v[c]);
        }
        float s = 0.0f;
        #pragma unroll
        for (int c = 0; c < NCLS; c++) s += expf(v[c] - m);
        float lse = m + logf(s);
        #pragma unroll
        for (int c = 0; c < NCLS; c++) loc[c] = v[c] - lse;
    }
    #pragma unroll
    for (int c = 0; c < NCLS; c++) sred[c * 256 + tid] = loc[c];
    __syncthreads();
    for (int st = 128; st > 0; st >>= 1) {
        if (tid < st) {
            #pragma unroll
            for (int c = 0; c < NCLS; c++)
                sred[c * 256 + tid] += sred[c * 256 + tid + st];
        }
        __syncthreads();
    }
    if (tid < NCLS) atomicAdd(&g_acc[tid], sred[tid * 256]);
}

__global__ void k_out(float* __restrict__ out) {
    int c = threadIdx.x;
    if (c < NCLS) out[c] = g_acc[c] * (1.0f / (float)NN);
}

// ---------------- launch ----------------
extern "C" void kernel_launch(void* const* d_in, const int* in_sizes, int n_in,
                              void* d_out, int out_size) {
    const float* x  = (const float*)d_in[0];
    const void*  ei = d_in[1];
    const float* W1 = (const float*)d_in[2];
    const float* b1 = (const float*)d_in[3];
    const float* W2 = (const float*)d_in[4];
    const float* b2 = (const float*)d_in[5];
    float* out = (float*)d_out;

    k_init        <<<(NN + 255) / 256, 256>>>(ei);
    k_edges_degree<<<(NE + 255) / 256, 256>>>(ei);
    k_scanA       <<<NB, 256>>>();
    k_scanB       <<<1, 512>>>();
    k_scanC       <<<(NN + 255) / 256, 256>>>();
    k_xhalf       <<<(NN * 32 + 255) / 256, 256>>>(x);
    k_fill        <<<(NE + 255) / 256, 256>>>();
    k_gather1     <<<(NN * 32 + 255) / 256, 256>>>();
    k_gemm1       <<<(NN + 63) / 64, 256>>>(W1, b1);
    k_gemm2       <<<(NN + 255) / 256, 256>>>(W2);
    k_gather2     <<<(NN * 32 + 255) / 256, 256>>>(b2);
    k_final       <<<(NN + 255) / 256, 256>>>();
    k_out         <<<1, 32>>>(out);
}